// round 1
// baseline (speedup 1.0000x reference)
#include <cuda_runtime.h>
#include <cuda_bf16.h>

// Problem constants (fixed shapes)
#define NODES 40000
#define EDGES 640000
#define DIN   128
#define HC    128   // H*C
#define OC    64    // out channels C

typedef unsigned long long ull;

// ---------------- device scratch (static; no runtime allocation) ----------
__device__ float        g_xm[(size_t)NODES * HC];     // x@W_msg + b_msg   (20.5 MB, L2-resident)
__device__ float        g_xs[(size_t)NODES * OC];     // x@W_self + b_self
__device__ float        g_alpha[(size_t)EDGES * 2];   // leaky-relu'd attention logits
__device__ unsigned int g_amax[(size_t)NODES * 2];    // per-(dst,head) max, as ordered uint key
__device__ float        g_denom[(size_t)NODES * 2];   // sum of exp
__device__ float        g_agg[(size_t)NODES * HC];    // unnormalized sum of ex*m
__device__ float        g_le_fallback[(size_t)EDGES * HC]; // used only if d_out doesn't hold le

// ---------------- helpers --------------------------------------------------
__device__ __forceinline__ ull pk2(float lo, float hi) {
    ull r; asm("mov.b64 %0,{%1,%2};" : "=l"(r) : "f"(lo), "f"(hi)); return r;
}
__device__ __forceinline__ void upk2(ull v, float& lo, float& hi) {
    asm("mov.b64 {%0,%1},%2;" : "=f"(lo), "=f"(hi) : "l"(v));
}
// Blackwell packed fp32 FMA: 2x fp32 throughput vs scalar FFMA
__device__ __forceinline__ void ffma2(ull& d, ull a, ull b) {
    asm("fma.rn.f32x2 %0,%1,%2,%0;" : "+l"(d) : "l"(a), "l"(b));
}
// order-preserving float->uint key for atomicMax
__device__ __forceinline__ unsigned int fkey(float f) {
    unsigned int u = __float_as_uint(f);
    return (u & 0x80000000u) ? ~u : (u | 0x80000000u);
}
__device__ __forceinline__ float funkey(unsigned int k) {
    unsigned int u = (k & 0x80000000u) ? (k & 0x7fffffffu) : ~k;
    return __uint_as_float(u);
}

// ---------------- K0: init accumulators ------------------------------------
__global__ void init_kernel() {
    int i = blockIdx.x * blockDim.x + threadIdx.x;
    if (i < NODES * HC) g_agg[i] = 0.0f;
    if (i < NODES * 2) { g_amax[i] = 0u; g_denom[i] = 0.0f; }
}

// ---------------- K1: node GEMMs  xm = x@W_msg+b_msg ; xs = x@W_self+b_self -
// 64 nodes per block, 256 threads. Whole W in smem (128 KB dynamic).
__global__ void node_kernel(const float* __restrict__ x,
                            const float* __restrict__ W_msg,
                            const float* __restrict__ b_msg,
                            const float* __restrict__ W_self,
                            const float* __restrict__ b_self) {
    extern __shared__ float sm[];
    float* Xs = sm;                 // 64*128
    float* Wm = sm + 64 * 128;      // 128*128
    float* Wf = Wm + 128 * 128;     // 128*64
    int tid = threadIdx.x;

    const float4* xg = (const float4*)(x + (size_t)blockIdx.x * 64 * DIN);
#pragma unroll
    for (int i = 0; i < 8; i++)  ((float4*)Xs)[tid + i * 256] = xg[tid + i * 256];
#pragma unroll
    for (int i = 0; i < 16; i++) ((float4*)Wm)[tid + i * 256] = ((const float4*)W_msg)[tid + i * 256];
#pragma unroll
    for (int i = 0; i < 8; i++)  ((float4*)Wf)[tid + i * 256] = ((const float4*)W_self)[tid + i * 256];
    __syncthreads();

    int lane = tid & 31, ty = tid >> 5;
    int lane4 = lane * 4;
    const float* Xr = Xs + ty * 8 * DIN;

    // ---- xm: 128 cols, 4 per lane ----
    {
        float acc[8][4];
#pragma unroll
        for (int r = 0; r < 8; r++) { acc[r][0] = acc[r][1] = acc[r][2] = acc[r][3] = 0.f; }
#pragma unroll 4
        for (int k = 0; k < 128; k++) {
            float4 bq = *(float4*)(Wm + k * 128 + lane4);
#pragma unroll
            for (int r = 0; r < 8; r++) {
                float av = Xr[r * DIN + k];
                acc[r][0] += av * bq.x; acc[r][1] += av * bq.y;
                acc[r][2] += av * bq.z; acc[r][3] += av * bq.w;
            }
        }
        float4 bm = *(const float4*)(b_msg + lane4);
#pragma unroll
        for (int r = 0; r < 8; r++) {
            int n = blockIdx.x * 64 + ty * 8 + r;
            float4 v; v.x = acc[r][0] + bm.x; v.y = acc[r][1] + bm.y;
            v.z = acc[r][2] + bm.z; v.w = acc[r][3] + bm.w;
            *(float4*)(g_xm + (size_t)n * HC + lane4) = v;
        }
    }
    // ---- xs: 64 cols, 2 per lane ----
    {
        int lane2 = lane * 2;
        float acc[8][2];
#pragma unroll
        for (int r = 0; r < 8; r++) { acc[r][0] = acc[r][1] = 0.f; }
#pragma unroll 4
        for (int k = 0; k < 128; k++) {
            float2 bq = *(float2*)(Wf + k * 64 + lane2);
#pragma unroll
            for (int r = 0; r < 8; r++) {
                float av = Xr[r * DIN + k];
                acc[r][0] += av * bq.x; acc[r][1] += av * bq.y;
            }
        }
        float2 bs = *(const float2*)(b_self + lane2);
#pragma unroll
        for (int r = 0; r < 8; r++) {
            int n = blockIdx.x * 64 + ty * 8 + r;
            float2 v; v.x = acc[r][0] + bs.x; v.y = acc[r][1] + bs.y;
            *(float2*)(g_xs + (size_t)n * OC + lane2) = v;
        }
    }
}

// ---------------- K2: edge GEMM + attention logits + segment max ------------
// le = edge_attr @ W_edge + b_edge  (written out)
// m  = le + g_xm[src]  ;  alpha = leaky_relu(sum_c m*att)  ;  atomicMax amax
// 64 edges/block, 256 threads, packed f32x2 FMAs. 96 KB dynamic smem.
__global__ void edge_kernel(const float* __restrict__ edge_attr,
                            const float* __restrict__ W_edge,
                            const float* __restrict__ b_edge,
                            const float* __restrict__ att,
                            const int*   __restrict__ srcIdx,
                            const int*   __restrict__ dstIdx,
                            float* __restrict__ le_out) {
    extern __shared__ float sm[];
    float* Ws = sm;             // 128*128
    float* As = sm + 128 * 128; // 64*128
    int tid = threadIdx.x;

#pragma unroll
    for (int i = 0; i < 16; i++) ((float4*)Ws)[tid + i * 256] = ((const float4*)W_edge)[tid + i * 256];
    const float4* Ag = (const float4*)(edge_attr + (size_t)blockIdx.x * 64 * DIN);
#pragma unroll
    for (int i = 0; i < 8; i++)  ((float4*)As)[tid + i * 256] = Ag[tid + i * 256];
    __syncthreads();

    int lane = tid & 31, ty = tid >> 5;
    int lane4 = lane * 4;
    const float* Ar = As + ty * 8 * DIN;

    ull acc[8][2];
#pragma unroll
    for (int r = 0; r < 8; r++) { acc[r][0] = 0ull; acc[r][1] = 0ull; }

#pragma unroll 4
    for (int k = 0; k < 128; k++) {
        float4 bq = *(float4*)(Ws + k * 128 + lane4);
        ull b01 = pk2(bq.x, bq.y);
        ull b23 = pk2(bq.z, bq.w);
#pragma unroll
        for (int r = 0; r < 8; r++) {
            float av = Ar[r * DIN + k];
            ull a2 = pk2(av, av);
            ffma2(acc[r][0], a2, b01);
            ffma2(acc[r][1], a2, b23);
        }
    }

    float4 be   = *(const float4*)(b_edge + lane4);
    float4 attv = *(const float4*)(att + lane4);
    int head = lane >> 4;

#pragma unroll
    for (int r = 0; r < 8; r++) {
        int e = blockIdx.x * 64 + ty * 8 + r;
        float c0, c1, c2, c3;
        upk2(acc[r][0], c0, c1);
        upk2(acc[r][1], c2, c3);
        float4 le; le.x = c0 + be.x; le.y = c1 + be.y; le.z = c2 + be.z; le.w = c3 + be.w;
        *(float4*)(le_out + (size_t)e * HC + lane4) = le;

        int s = srcIdx[e];
        float4 xv = *(const float4*)(g_xm + (size_t)s * HC + lane4);
        float m0 = le.x + xv.x, m1 = le.y + xv.y, m2 = le.z + xv.z, m3 = le.w + xv.w;
        float p = m0 * attv.x + m1 * attv.y + m2 * attv.z + m3 * attv.w;
        // reduce within each 16-lane half (head 0 = lanes 0..15, head 1 = 16..31)
        p += __shfl_xor_sync(0xffffffffu, p, 1);
        p += __shfl_xor_sync(0xffffffffu, p, 2);
        p += __shfl_xor_sync(0xffffffffu, p, 4);
        p += __shfl_xor_sync(0xffffffffu, p, 8);
        if ((lane & 15) == 0) {
            float lr = p > 0.0f ? p : 0.2f * p;   // leaky_relu(0.2)
            g_alpha[(size_t)e * 2 + head] = lr;
            int d = dstIdx[e];
            atomicMax(&g_amax[d * 2 + head], fkey(lr));
        }
    }
}

// ---------------- K3: exp + unnormalized weighted scatter-add ---------------
// One warp per edge: denom[dst,h] += ex ; agg[dst,h,c] += ex * m
__global__ void scatter_kernel(const float* __restrict__ le,
                               const int* __restrict__ srcIdx,
                               const int* __restrict__ dstIdx) {
    int w = blockIdx.x * 8 + (threadIdx.x >> 5);
    if (w >= EDGES) return;
    int lane = threadIdx.x & 31;
    int lane4 = lane * 4;
    int e = w;

    float4 lv = *(const float4*)(le + (size_t)e * HC + lane4);
    int s = srcIdx[e];
    int d = dstIdx[e];
    float4 xv = *(const float4*)(g_xm + (size_t)s * HC + lane4);
    float m0 = lv.x + xv.x, m1 = lv.y + xv.y, m2 = lv.z + xv.z, m3 = lv.w + xv.w;

    int head = lane >> 4;
    float alpha = g_alpha[(size_t)e * 2 + head];
    float amax  = funkey(g_amax[d * 2 + head]);
    float ex = __expf(alpha - amax);

    if ((lane & 15) == 0) atomicAdd(&g_denom[d * 2 + head], ex);
    float* ag = g_agg + (size_t)d * HC + lane4;
    atomicAdd(ag + 0, m0 * ex);
    atomicAdd(ag + 1, m1 * ex);
    atomicAdd(ag + 2, m2 * ex);
    atomicAdd(ag + 3, m3 * ex);
}

// ---------------- K4: finalize  out = mean_h(agg/denom) + xs ----------------
__global__ void finalize_kernel(float* __restrict__ out) {
    int i = blockIdx.x * blockDim.x + threadIdx.x;
    if (i >= NODES * OC) return;
    int n = i >> 6;
    int c = i & 63;
    float d0 = g_denom[n * 2 + 0] + 1e-16f;
    float d1 = g_denom[n * 2 + 1] + 1e-16f;
    float v = 0.5f * (g_agg[(size_t)n * HC + c] / d0 + g_agg[(size_t)n * HC + 64 + c] / d1);
    out[i] = v + g_xs[i];
}

// ---------------- launch ----------------------------------------------------
extern "C" void kernel_launch(void* const* d_in, const int* in_sizes, int n_in,
                              void* d_out, int out_size) {
    const float* x        = (const float*)d_in[0];
    const float* edge_attr= (const float*)d_in[1];
    const float* W_msg    = (const float*)d_in[2];
    const float* b_msg    = (const float*)d_in[3];
    const float* W_edge   = (const float*)d_in[4];
    const float* b_edge   = (const float*)d_in[5];
    const float* W_self   = (const float*)d_in[6];
    const float* b_self   = (const float*)d_in[7];
    const float* att      = (const float*)d_in[8];
    const int*   ei       = (const int*)d_in[9];
    const int* srcI = ei;
    const int* dstI = ei + EDGES;

    float* out = (float*)d_out;
    // Output layout: [out (N*OC floats)][le (E*HC floats)] if the buffer is big
    // enough for both returns; otherwise keep le in device scratch.
    float* le_out;
    bool le_in_out = (out_size >= NODES * OC + (long long)EDGES * HC);
    if (le_in_out) {
        le_out = out + (size_t)NODES * OC;
    } else {
        void* p = nullptr;
        cudaGetSymbolAddress(&p, g_le_fallback);
        le_out = (float*)p;
    }

    cudaFuncSetAttribute(node_kernel, cudaFuncAttributeMaxDynamicSharedMemorySize, 131072);
    cudaFuncSetAttribute(edge_kernel, cudaFuncAttributeMaxDynamicSharedMemorySize, 98304);

    init_kernel<<<(NODES * HC + 255) / 256, 256>>>();
    node_kernel<<<NODES / 64, 256, 131072>>>(x, W_msg, b_msg, W_self, b_self);
    edge_kernel<<<EDGES / 64, 256, 98304>>>(edge_attr, W_edge, b_edge, att, srcI, dstI, le_out);
    scatter_kernel<<<EDGES / 8, 256>>>(le_out, srcI, dstI);
    finalize_kernel<<<(NODES * OC + 255) / 256, 256>>>(out);
}

// round 2
// speedup vs baseline: 1.3413x; 1.3413x over previous
#include <cuda_runtime.h>
#include <cuda_bf16.h>

// Problem constants (fixed shapes)
#define NODES 40000
#define EDGES 640000
#define DIN   128
#define HC    128   // H*C
#define OC    64    // out channels C

typedef unsigned long long ull;

// ---------------- device scratch (static; no runtime allocation) ----------
__device__ float g_xm[(size_t)NODES * HC];     // x@W_msg + b_msg (20.5 MB, L2-resident)
__device__ float g_xs[(size_t)NODES * OC];     // x@W_self + b_self
__device__ float g_denom[(size_t)NODES * 2];   // sum of exp (unnormalized)
__device__ float g_agg[(size_t)NODES * HC];    // sum of ex*m (unnormalized)
__device__ float g_le_fallback[(size_t)EDGES * HC];

// ---------------- helpers --------------------------------------------------
__device__ __forceinline__ ull pk2(float lo, float hi) {
    ull r; asm("mov.b64 %0,{%1,%2};" : "=l"(r) : "f"(lo), "f"(hi)); return r;
}
__device__ __forceinline__ void upk2(ull v, float& lo, float& hi) {
    asm("mov.b64 {%0,%1},%2;" : "=f"(lo), "=f"(hi) : "l"(v));
}
// Blackwell packed fp32 FMA: 2x fp32 throughput vs scalar FFMA
__device__ __forceinline__ void ffma2(ull& d, ull a, ull b) {
    asm("fma.rn.f32x2 %0,%1,%2,%0;" : "+l"(d) : "l"(a), "l"(b));
}
// vector reduction atomic: 1 transaction for 4 floats
__device__ __forceinline__ void red_add_v4(float* p, float a, float b, float c, float d) {
    asm volatile("red.global.add.v4.f32 [%0], {%1,%2,%3,%4};"
                 :: "l"(p), "f"(a), "f"(b), "f"(c), "f"(d) : "memory");
}
__device__ __forceinline__ void red_add_f32(float* p, float v) {
    asm volatile("red.global.add.f32 [%0], %1;" :: "l"(p), "f"(v) : "memory");
}

// ---------------- K0: init accumulators ------------------------------------
__global__ void init_kernel() {
    int i = blockIdx.x * blockDim.x + threadIdx.x;
    if (i < NODES * HC) g_agg[i] = 0.0f;
    if (i < NODES * 2)  g_denom[i] = 0.0f;
}

// ---------------- K1: node GEMMs  xm = x@W_msg+b_msg ; xs = x@W_self+b_self -
__global__ void node_kernel(const float* __restrict__ x,
                            const float* __restrict__ W_msg,
                            const float* __restrict__ b_msg,
                            const float* __restrict__ W_self,
                            const float* __restrict__ b_self) {
    extern __shared__ float sm[];
    float* Xs = sm;                 // 64*128
    float* Wm = sm + 64 * 128;      // 128*128
    float* Wf = Wm + 128 * 128;     // 128*64
    int tid = threadIdx.x;

    const float4* xg = (const float4*)(x + (size_t)blockIdx.x * 64 * DIN);
#pragma unroll
    for (int i = 0; i < 8; i++)  ((float4*)Xs)[tid + i * 256] = xg[tid + i * 256];
#pragma unroll
    for (int i = 0; i < 16; i++) ((float4*)Wm)[tid + i * 256] = ((const float4*)W_msg)[tid + i * 256];
#pragma unroll
    for (int i = 0; i < 8; i++)  ((float4*)Wf)[tid + i * 256] = ((const float4*)W_self)[tid + i * 256];
    __syncthreads();

    int lane = tid & 31, ty = tid >> 5;
    int lane4 = lane * 4;
    const float* Xr = Xs + ty * 8 * DIN;

    // ---- xm: 128 cols, 4 per lane ----
    {
        float acc[8][4];
#pragma unroll
        for (int r = 0; r < 8; r++) { acc[r][0] = acc[r][1] = acc[r][2] = acc[r][3] = 0.f; }
#pragma unroll 4
        for (int k = 0; k < 128; k++) {
            float4 bq = *(float4*)(Wm + k * 128 + lane4);
#pragma unroll
            for (int r = 0; r < 8; r++) {
                float av = Xr[r * DIN + k];
                acc[r][0] += av * bq.x; acc[r][1] += av * bq.y;
                acc[r][2] += av * bq.z; acc[r][3] += av * bq.w;
            }
        }
        float4 bm = *(const float4*)(b_msg + lane4);
#pragma unroll
        for (int r = 0; r < 8; r++) {
            int n = blockIdx.x * 64 + ty * 8 + r;
            float4 v; v.x = acc[r][0] + bm.x; v.y = acc[r][1] + bm.y;
            v.z = acc[r][2] + bm.z; v.w = acc[r][3] + bm.w;
            *(float4*)(g_xm + (size_t)n * HC + lane4) = v;
        }
    }
    // ---- xs: 64 cols, 2 per lane ----
    {
        int lane2 = lane * 2;
        float acc[8][2];
#pragma unroll
        for (int r = 0; r < 8; r++) { acc[r][0] = acc[r][1] = 0.f; }
#pragma unroll 4
        for (int k = 0; k < 128; k++) {
            float2 bq = *(float2*)(Wf + k * 64 + lane2);
#pragma unroll
            for (int r = 0; r < 8; r++) {
                float av = Xr[r * DIN + k];
                acc[r][0] += av * bq.x; acc[r][1] += av * bq.y;
            }
        }
        float2 bs = *(const float2*)(b_self + lane2);
#pragma unroll
        for (int r = 0; r < 8; r++) {
            int n = blockIdx.x * 64 + ty * 8 + r;
            float2 v; v.x = acc[r][0] + bs.x; v.y = acc[r][1] + bs.y;
            *(float2*)(g_xs + (size_t)n * OC + lane2) = v;
        }
    }
}

// ---------------- K2 (FUSED): edge GEMM + attention + exp + scatter ---------
// le = edge_attr @ W_edge + b_edge   (written out)
// m  = le + g_xm[src]
// alpha = leaky_relu(sum_c m*att)  -> ex = exp(alpha)   (no max-shift; the
//   e^amax factor cancels in agg/denom, and |alpha| <~ 15 so exp is safe)
// agg[dst] += ex*m ; denom[dst] += ex   via vector reduction atomics.
__global__ void edge_kernel(const float* __restrict__ edge_attr,
                            const float* __restrict__ W_edge,
                            const float* __restrict__ b_edge,
                            const float* __restrict__ att,
                            const int*   __restrict__ srcIdx,
                            const int*   __restrict__ dstIdx,
                            float* __restrict__ le_out) {
    extern __shared__ float sm[];
    float* Ws = sm;             // 128*128
    float* As = sm + 128 * 128; // 64*128
    int tid = threadIdx.x;

#pragma unroll
    for (int i = 0; i < 16; i++) ((float4*)Ws)[tid + i * 256] = ((const float4*)W_edge)[tid + i * 256];
    const float4* Ag = (const float4*)(edge_attr + (size_t)blockIdx.x * 64 * DIN);
#pragma unroll
    for (int i = 0; i < 8; i++)  ((float4*)As)[tid + i * 256] = Ag[tid + i * 256];
    __syncthreads();

    int lane = tid & 31, ty = tid >> 5;
    int lane4 = lane * 4;
    const float* Ar = As + ty * 8 * DIN;

    ull acc[8][2];
#pragma unroll
    for (int r = 0; r < 8; r++) { acc[r][0] = 0ull; acc[r][1] = 0ull; }

#pragma unroll 4
    for (int k = 0; k < 128; k++) {
        float4 bq = *(float4*)(Ws + k * 128 + lane4);
        ull b01 = pk2(bq.x, bq.y);
        ull b23 = pk2(bq.z, bq.w);
#pragma unroll
        for (int r = 0; r < 8; r++) {
            float av = Ar[r * DIN + k];
            ull a2 = pk2(av, av);
            ffma2(acc[r][0], a2, b01);
            ffma2(acc[r][1], a2, b23);
        }
    }

    float4 be   = *(const float4*)(b_edge + lane4);
    float4 attv = *(const float4*)(att + lane4);
    int head = lane >> 4;

#pragma unroll
    for (int r = 0; r < 8; r++) {
        int e = blockIdx.x * 64 + ty * 8 + r;
        float c0, c1, c2, c3;
        upk2(acc[r][0], c0, c1);
        upk2(acc[r][1], c2, c3);
        float4 le; le.x = c0 + be.x; le.y = c1 + be.y; le.z = c2 + be.z; le.w = c3 + be.w;
        *(float4*)(le_out + (size_t)e * HC + lane4) = le;

        int s = srcIdx[e];
        int d = dstIdx[e];
        float4 xv = *(const float4*)(g_xm + (size_t)s * HC + lane4);
        float m0 = le.x + xv.x, m1 = le.y + xv.y, m2 = le.z + xv.z, m3 = le.w + xv.w;
        float p = m0 * attv.x + m1 * attv.y + m2 * attv.z + m3 * attv.w;
        // butterfly within each 16-lane half: every lane gets its head's full dot
        p += __shfl_xor_sync(0xffffffffu, p, 1);
        p += __shfl_xor_sync(0xffffffffu, p, 2);
        p += __shfl_xor_sync(0xffffffffu, p, 4);
        p += __shfl_xor_sync(0xffffffffu, p, 8);
        float lr = p > 0.0f ? p : 0.2f * p;   // leaky_relu(0.2)
        float ex = __expf(lr);

        red_add_v4(g_agg + (size_t)d * HC + lane4, m0 * ex, m1 * ex, m2 * ex, m3 * ex);
        if ((lane & 15) == 0) red_add_f32(&g_denom[d * 2 + head], ex);
    }
}

// ---------------- K3: finalize  out = mean_h(agg/denom) + xs ----------------
__global__ void finalize_kernel(float* __restrict__ out) {
    int i = blockIdx.x * blockDim.x + threadIdx.x;
    if (i >= NODES * OC) return;
    int n = i >> 6;
    int c = i & 63;
    float d0 = g_denom[n * 2 + 0] + 1e-16f;
    float d1 = g_denom[n * 2 + 1] + 1e-16f;
    float v = 0.5f * (g_agg[(size_t)n * HC + c] / d0 + g_agg[(size_t)n * HC + 64 + c] / d1);
    out[i] = v + g_xs[i];
}

// ---------------- launch ----------------------------------------------------
extern "C" void kernel_launch(void* const* d_in, const int* in_sizes, int n_in,
                              void* d_out, int out_size) {
    const float* x        = (const float*)d_in[0];
    const float* edge_attr= (const float*)d_in[1];
    const float* W_msg    = (const float*)d_in[2];
    const float* b_msg    = (const float*)d_in[3];
    const float* W_edge   = (const float*)d_in[4];
    const float* b_edge   = (const float*)d_in[5];
    const float* W_self   = (const float*)d_in[6];
    const float* b_self   = (const float*)d_in[7];
    const float* att      = (const float*)d_in[8];
    const int*   ei       = (const int*)d_in[9];
    const int* srcI = ei;
    const int* dstI = ei + EDGES;

    float* out = (float*)d_out;
    float* le_out;
    bool le_in_out = (out_size >= NODES * OC + (long long)EDGES * HC);
    if (le_in_out) {
        le_out = out + (size_t)NODES * OC;
    } else {
        void* p = nullptr;
        cudaGetSymbolAddress(&p, g_le_fallback);
        le_out = (float*)p;
    }

    cudaFuncSetAttribute(node_kernel, cudaFuncAttributeMaxDynamicSharedMemorySize, 131072);
    cudaFuncSetAttribute(edge_kernel, cudaFuncAttributeMaxDynamicSharedMemorySize, 98304);

    init_kernel<<<(NODES * HC + 255) / 256, 256>>>();
    node_kernel<<<NODES / 64, 256, 131072>>>(x, W_msg, b_msg, W_self, b_self);
    edge_kernel<<<EDGES / 64, 256, 98304>>>(edge_attr, W_edge, b_edge, att, srcI, dstI, le_out);
    finalize_kernel<<<(NODES * OC + 255) / 256, 256>>>(out);
}